// round 10
// baseline (speedup 1.0000x reference)
#include <cuda_runtime.h>
#include <cuda_bf16.h>
#include <math.h>

// Problem constants (fixed shapes for this problem)
#define BB 4
#define HH 1024
#define WW 1920
#define HW (HH * WW)                 // 1,966,080
#define NPIX (BB * HW)               // 7,864,320
#define ALPHA 100.0f
#define EPSN 1e-7f

// Scratch accumulator: [B][H][W][4] channel-interleaved, 16B aligned per pixel.
// 4 * 7,864,320 floats = ~125.8 MB static device allocation (allowed).
__device__ __align__(16) float g_acc[(size_t)NPIX * 4];

__global__ void __launch_bounds__(256)
splat_metric_kernel(const float* __restrict__ rgb1,
                    const float* __restrict__ rgb2,
                    const float* __restrict__ flow_t,
                    const float* __restrict__ flow12,
                    float* __restrict__ out_metric)
{
    int i = blockIdx.x * blockDim.x + threadIdx.x;
    if (i >= NPIX) return;

    int b   = i / HW;
    int rem = i - b * HW;
    int y   = rem / WW;
    int x   = rem - y * WW;

    // ---- Backwarp rgb2 with flow12 (bilinear gather, zeros padding) ----
    const float* f12 = flow12 + b * 2 * HW;
    float px = (float)x + f12[rem];
    float py = (float)y + f12[HW + rem];
    float x0f = floorf(px), y0f = floorf(py);
    int   x0  = (int)x0f,   y0  = (int)y0f;
    float wx  = px - x0f,   wy  = py - y0f;

    const float* r2 = rgb2 + b * 3 * HW;
    float bw0 = 0.f, bw1 = 0.f, bw2 = 0.f;
    {
        float wtx[2] = {1.f - wx, wx};
        float wty[2] = {1.f - wy, wy};
        #pragma unroll
        for (int ty = 0; ty < 2; ty++) {
            int yi = y0 + ty;
            if (yi < 0 || yi >= HH) continue;
            #pragma unroll
            for (int tx = 0; tx < 2; tx++) {
                int xi = x0 + tx;
                if (xi < 0 || xi >= WW) continue;
                float w = wtx[tx] * wty[ty];
                int idx = yi * WW + xi;
                bw0 += w * __ldg(r2 + idx);
                bw1 += w * __ldg(r2 + HW + idx);
                bw2 += w * __ldg(r2 + 2 * HW + idx);
            }
        }
    }

    // ---- Metric: per-pixel channel-mean L1 ----
    const float* r1 = rgb1 + b * 3 * HW;
    float c0 = r1[rem];
    float c1 = r1[HW + rem];
    float c2 = r1[2 * HW + rem];
    float metric = (fabsf(c0 - bw0) + fabsf(c1 - bw1) + fabsf(c2 - bw2)) / 3.0f;
    out_metric[i] = metric;

    float m  = fminf(fmaxf(-ALPHA * metric, -ALPHA), ALPHA);
    float em = __expf(m) ;
    // use precise expf to stay well inside 1e-3 (fast exp has ~2 ulp; fine, but
    // metric feeds output directly so keep it tight):
    em = expf(m);

    // ---- Forward splat (bilinear scatter-add) with flow_t ----
    const float* ft = flow_t + b * 2 * HW;
    float qx = (float)x + ft[rem];
    float qy = (float)y + ft[HW + rem];
    float qx0f = floorf(qx), qy0f = floorf(qy);
    int   qx0  = (int)qx0f,  qy0  = (int)qy0f;
    float ux   = qx - qx0f,  uy   = qy - qy0f;

    float4 v = make_float4(c0 * em, c1 * em, c2 * em, em);
    float* acc = g_acc + (size_t)b * HW * 4;

    float utx[2] = {1.f - ux, ux};
    float uty[2] = {1.f - uy, uy};
    #pragma unroll
    for (int ty = 0; ty < 2; ty++) {
        int yi = qy0 + ty;
        if (yi < 0 || yi >= HH) continue;
        #pragma unroll
        for (int tx = 0; tx < 2; tx++) {
            int xi = qx0 + tx;
            if (xi < 0 || xi >= WW) continue;
            float w = utx[tx] * uty[ty];
            float4* p = (float4*)(acc + (size_t)(yi * WW + xi) * 4);
            atomicAdd(p, make_float4(v.x * w, v.y * w, v.z * w, v.w * w));
        }
    }
}

__global__ void __launch_bounds__(256)
normalize_kernel(float* __restrict__ out_img)
{
    int i = blockIdx.x * blockDim.x + threadIdx.x;
    if (i >= NPIX) return;

    float4 v = *(const float4*)(g_acc + (size_t)i * 4);
    float inv = 1.0f / (v.w + EPSN);

    int b   = i / HW;
    int rem = i - b * HW;
    float* o = out_img + b * 3 * HW;
    o[rem]          = v.x * inv;
    o[HW + rem]     = v.y * inv;
    o[2 * HW + rem] = v.z * inv;
}

extern "C" void kernel_launch(void* const* d_in, const int* in_sizes, int n_in,
                              void* d_out, int out_size)
{
    const float* rgb1   = (const float*)d_in[0];
    const float* rgb2   = (const float*)d_in[1];
    const float* flow_t = (const float*)d_in[2];  // flow_src1_to_tgt
    const float* flow12 = (const float*)d_in[3];  // flow_src1_to_src2

    float* out_img    = (float*)d_out;                        // [B,3,H,W]
    float* out_metric = (float*)d_out + (size_t)BB * 3 * HW;  // [B,1,H,W]

    void* acc_ptr = nullptr;
    cudaGetSymbolAddress(&acc_ptr, g_acc);
    cudaMemsetAsync(acc_ptr, 0, (size_t)NPIX * 4 * sizeof(float), 0);

    const int threads = 256;
    const int blocks  = (NPIX + threads - 1) / threads;

    splat_metric_kernel<<<blocks, threads, 0, 0>>>(rgb1, rgb2, flow_t, flow12, out_metric);
    normalize_kernel<<<blocks, threads, 0, 0>>>(out_img);
}